// round 2
// baseline (speedup 1.0000x reference)
#include <cuda_runtime.h>

// Problem constants (fixed shapes)
#define BB 8
#define CC 64
#define SS 16
#define HH 256
#define WW 256
#define HWN 65536
#define NCHUNK 128          // reduction chunks per batch (512 px each)
#define PART_STRIDE 1296    // 256 gram + 1024 G + 16 r

// ---------------- device scratch (no allocations allowed) ----------------
__device__ __align__(16) float g_U[BB * SS * HWN];              // conv1 output (33.5 MB)
__device__ __align__(16) float g_part[BB * NCHUNK * PART_STRIDE];
__device__ __align__(16) float g_PF2[BB * SS * CC];
__device__ __align__(16) float g_Wt_sub[128 * 9 * 16];          // [ic*9+tap][oc]
__device__ __align__(16) float g_Wt_cb[128 * 9 * 64];

// ---------------- weight pre-transpose: [oc][ic][tap] -> [ic*9+tap][oc] ----------------
__global__ void transpose_w_kernel(const float* __restrict__ Ws,
                                   const float* __restrict__ Wc) {
    int idx = blockIdx.x * 256 + threadIdx.x;
    if (idx < 16 * 1152) {
        int oc = idx / 1152; int r = idx - oc * 1152;
        g_Wt_sub[r * 16 + oc] = Ws[idx];
    }
    if (idx < 64 * 1152) {
        int oc = idx / 1152; int r = idx - oc * 1152;
        g_Wt_cb[r * 64 + oc] = Wc[idx];
    }
}

// ---------------- conv1: U = conv3x3(cat(x,bridge), W_sub), 128->16 ----------------
// tile 32x32 pixels, 256 threads, each thread: 4 rows x 1 col x 16 oc
__global__ __launch_bounds__(256, 2)
void conv1_kernel(const float* __restrict__ x, const float* __restrict__ bridge) {
    __shared__ __align__(16) float sIn[8][34][36];
    __shared__ __align__(16) float sW[8][9][16];

    int b = blockIdx.z;
    int by0 = blockIdx.y * 32, bx0 = blockIdx.x * 32;
    int tid = threadIdx.x;
    int pcol = tid & 31;
    int prow = tid >> 5;          // 0..7
    int ybase = prow * 4;

    float acc[4][16];
#pragma unroll
    for (int d = 0; d < 4; d++)
#pragma unroll
        for (int o = 0; o < 16; o++) acc[d][o] = 0.f;

    for (int k = 0; k < 16; k++) {
        const float* src = (k < 8) ? x : bridge;
        int cb = (k & 7) * 8;
        // stage 8-channel input tile with halo
        for (int idx = tid; idx < 8 * 34 * 34; idx += 256) {
            int c = idx / 1156; int rem = idx - c * 1156;
            int r = rem / 34;   int cc2 = rem - r * 34;
            int gy = by0 - 1 + r, gx = bx0 - 1 + cc2;
            float v = 0.f;
            if (gy >= 0 && gy < HH && gx >= 0 && gx < WW)
                v = src[(size_t)(b * 64 + cb + c) * HWN + gy * WW + gx];
            sIn[c][r][cc2] = v;
        }
        // stage weights (contiguous chunk of pre-transposed layout)
        for (int idx = tid; idx < 1152; idx += 256)
            ((float*)sW)[idx] = g_Wt_sub[k * 1152 + idx];
        __syncthreads();

#pragma unroll
        for (int c = 0; c < 8; c++) {
#pragma unroll
            for (int ky = 0; ky < 3; ky++) {
#pragma unroll
                for (int kx = 0; kx < 3; kx++) {
                    float iv0 = sIn[c][ybase + ky + 0][pcol + kx];
                    float iv1 = sIn[c][ybase + ky + 1][pcol + kx];
                    float iv2 = sIn[c][ybase + ky + 2][pcol + kx];
                    float iv3 = sIn[c][ybase + ky + 3][pcol + kx];
                    const float4* wp = reinterpret_cast<const float4*>(&sW[c][ky * 3 + kx][0]);
                    float wv[16];
                    *reinterpret_cast<float4*>(&wv[0])  = wp[0];
                    *reinterpret_cast<float4*>(&wv[4])  = wp[1];
                    *reinterpret_cast<float4*>(&wv[8])  = wp[2];
                    *reinterpret_cast<float4*>(&wv[12]) = wp[3];
#pragma unroll
                    for (int o = 0; o < 16; o++) {
                        acc[0][o] += iv0 * wv[o];
                        acc[1][o] += iv1 * wv[o];
                        acc[2][o] += iv2 * wv[o];
                        acc[3][o] += iv3 * wv[o];
                    }
                }
            }
        }
        __syncthreads();
    }

#pragma unroll
    for (int d = 0; d < 4; d++) {
        int y = by0 + ybase + d;
        int xg = bx0 + pcol;
#pragma unroll
        for (int s2 = 0; s2 < 16; s2++)
            g_U[((b * 16 + s2) << 16) + (y << 8) + xg] = acc[d][s2];
    }
}

// ---------------- reduction: Gram[16,16], G[16,64], r[16] partials per 512-px chunk ----------------
__global__ __launch_bounds__(256)
void reduce_kernel(const float* __restrict__ bridge) {
    __shared__ __align__(16) float sU[16][68];
    __shared__ __align__(16) float sB[64][68];

    int b = blockIdx.y, ch = blockIdx.x;
    int tid = threadIdx.x;
    int s = tid >> 4, q = tid & 15;
    int n0 = ch * 512;

    const float* Ub = g_U + (size_t)b * 16 * HWN;
    const float* Bb = bridge + (size_t)b * 64 * HWN;

    float accG[4] = {0.f, 0.f, 0.f, 0.f};
    float accM = 0.f;
    float accR = 0.f;

    for (int sub = 0; sub < 8; sub++) {
        int n = n0 + sub * 64;
        {
            int sl = tid >> 4, p4 = (tid & 15) * 4;
            *reinterpret_cast<float4*>(&sU[sl][p4]) =
                *reinterpret_cast<const float4*>(&Ub[sl * HWN + n + p4]);
        }
#pragma unroll
        for (int r = 0; r < 4; r++) {
            int cl = (tid >> 4) + r * 16;
            int p4 = (tid & 15) * 4;
            *reinterpret_cast<float4*>(&sB[cl][p4]) =
                *reinterpret_cast<const float4*>(&Bb[cl * HWN + n + p4]);
        }
        __syncthreads();
#pragma unroll
        for (int p = 0; p < 64; p += 4) {
            float4 u  = *reinterpret_cast<float4*>(&sU[s][p]);
            float4 t4 = *reinterpret_cast<float4*>(&sU[q][p]);
            accM += u.x * t4.x + u.y * t4.y + u.z * t4.z + u.w * t4.w;
#pragma unroll
            for (int j = 0; j < 4; j++) {
                float4 bv = *reinterpret_cast<float4*>(&sB[q + j * 16][p]);
                accG[j] += u.x * bv.x + u.y * bv.y + u.z * bv.z + u.w * bv.w;
            }
            if (q == 0)
                accR += fabsf(u.x) + fabsf(u.y) + fabsf(u.z) + fabsf(u.w);
        }
        __syncthreads();
    }

    float* out = g_part + (size_t)(b * NCHUNK + ch) * PART_STRIDE;
    out[s * 16 + q] = accM;
#pragma unroll
    for (int j = 0; j < 4; j++)
        out[256 + s * 64 + q + j * 16] = accG[j];
    if (q == 0) out[1280 + s] = accR;
}

// ---------------- solve: mat = D^-1 Gram D^-1; PF2 = D^-1 mat^-1 D^-1 G ----------------
__global__ __launch_bounds__(256)
void solve_kernel() {
    __shared__ float sGram[256];
    __shared__ float sG[1024];
    __shared__ float srr[16];
    __shared__ double A[16][17];
    __shared__ double M[16][17];
    __shared__ double spiv;

    int b = blockIdx.x;
    int tid = threadIdx.x;
    const float* base = g_part + (size_t)b * NCHUNK * PART_STRIDE;

    {
        float a = 0.f;
        for (int ch = 0; ch < NCHUNK; ch++) a += base[ch * PART_STRIDE + tid];
        sGram[tid] = a;
    }
#pragma unroll
    for (int j = 0; j < 4; j++) {
        int e = tid + j * 256;
        float a = 0.f;
        for (int ch = 0; ch < NCHUNK; ch++) a += base[ch * PART_STRIDE + 256 + e];
        sG[e] = a;
    }
    if (tid < 16) {
        float a = 0.f;
        for (int ch = 0; ch < NCHUNK; ch++) a += base[ch * PART_STRIDE + 1280 + tid];
        srr[tid] = 1e-6f + a;
    }
    __syncthreads();

    {
        int i = tid >> 4, t = tid & 15;
        A[i][t] = (double)sGram[tid] / ((double)srr[i] * (double)srr[t]);
        M[i][t] = (i == t) ? 1.0 : 0.0;
    }
    __syncthreads();

    // Gauss-Jordan (SPD, no pivoting), parallel over 256 threads
    for (int k = 0; k < 16; k++) {
        if (tid == 0) spiv = 1.0 / A[k][k];
        __syncthreads();
        if (tid < 16) { A[k][tid] *= spiv; M[k][tid] *= spiv; }
        __syncthreads();
        int i = tid >> 4, t = tid & 15;
        double f = A[i][k];
        __syncthreads();
        if (i != k) {
            A[i][t] -= f * A[k][t];
            M[i][t] -= f * M[k][t];
        }
        __syncthreads();
    }

#pragma unroll
    for (int j = 0; j < 4; j++) {
        int e = tid + j * 256;
        int s = e >> 6, c = e & 63;
        double v = 0.0;
#pragma unroll
        for (int t = 0; t < 16; t++)
            v += M[s][t] * ((double)sG[t * 64 + c] / (double)srr[t]);
        g_PF2[b * 1024 + e] = (float)(v / (double)srr[s]);
    }
}

// ---------------- conv2 (fused): out = conv3x3(cat(x, U^T*PF2), W_cb) + x ----------------
// tile 16x16 pixels, 256 threads = 4 oc-groups x 64 pixel-slots (4 rows each)
__global__ __launch_bounds__(256, 2)
void conv2_kernel(const float* __restrict__ x, float* __restrict__ out) {
    __shared__ float sU[16][18][20];
    __shared__ float sInC[4][18][20];
    __shared__ __align__(16) float sWC[4][9][64];
    __shared__ float sPF[1024];

    int b = blockIdx.z;
    int by0 = blockIdx.y * 16, bx0 = blockIdx.x * 16;
    int tid = threadIdx.x;
    int pcol = tid & 15;
    int prow = (tid >> 4) & 3;
    int g = tid >> 6;             // oc group 0..3
    int ybase = prow * 4;

    for (int idx = tid; idx < 1024; idx += 256) sPF[idx] = g_PF2[b * 1024 + idx];
    for (int idx = tid; idx < 16 * 324; idx += 256) {
        int s2 = idx / 324; int rem = idx - s2 * 324;
        int r = rem / 18;   int cc2 = rem - r * 18;
        int gy = by0 - 1 + r, gx = bx0 - 1 + cc2;
        float v = 0.f;
        if (gy >= 0 && gy < HH && gx >= 0 && gx < WW)
            v = g_U[((b * 16 + s2) << 16) + (gy << 8) + gx];
        sU[s2][r][cc2] = v;
    }

    float acc[4][16];
#pragma unroll
    for (int d = 0; d < 4; d++)
#pragma unroll
        for (int o = 0; o < 16; o++) acc[d][o] = 0.f;
    __syncthreads();

    for (int k = 0; k < 32; k++) {
        // weights: contiguous chunk
        for (int idx = tid; idx < 2304; idx += 256)
            ((float*)sWC)[idx] = g_Wt_cb[k * 2304 + idx];
        if (k < 16) {
            int cb = k * 4;
            for (int idx = tid; idx < 4 * 324; idx += 256) {
                int c = idx / 324; int rem = idx - c * 324;
                int r = rem / 18;  int cc2 = rem - r * 18;
                int gy = by0 - 1 + r, gx = bx0 - 1 + cc2;
                float v = 0.f;
                if (gy >= 0 && gy < HH && gx >= 0 && gx < WW)
                    v = x[(size_t)(b * 64 + cb + c) * HWN + gy * WW + gx];
                sInC[c][r][cc2] = v;
            }
        } else {
            int cpb = (k - 16) * 4;  // projected-channel base
            for (int idx = tid; idx < 4 * 324; idx += 256) {
                int c = idx / 324; int rem = idx - c * 324;
                int r = rem / 18;  int cc2 = rem - r * 18;
                float v = 0.f;
#pragma unroll
                for (int s2 = 0; s2 < 16; s2++)
                    v += sU[s2][r][cc2] * sPF[s2 * 64 + cpb + c];
                sInC[c][r][cc2] = v;
            }
        }
        __syncthreads();

#pragma unroll
        for (int c = 0; c < 4; c++) {
#pragma unroll
            for (int ky = 0; ky < 3; ky++) {
#pragma unroll
                for (int kx = 0; kx < 3; kx++) {
                    float iv0 = sInC[c][ybase + ky + 0][pcol + kx];
                    float iv1 = sInC[c][ybase + ky + 1][pcol + kx];
                    float iv2 = sInC[c][ybase + ky + 2][pcol + kx];
                    float iv3 = sInC[c][ybase + ky + 3][pcol + kx];
                    const float4* wp =
                        reinterpret_cast<const float4*>(&sWC[c][ky * 3 + kx][g * 16]);
                    float wv[16];
                    *reinterpret_cast<float4*>(&wv[0])  = wp[0];
                    *reinterpret_cast<float4*>(&wv[4])  = wp[1];
                    *reinterpret_cast<float4*>(&wv[8])  = wp[2];
                    *reinterpret_cast<float4*>(&wv[12]) = wp[3];
#pragma unroll
                    for (int o = 0; o < 16; o++) {
                        acc[0][o] += iv0 * wv[o];
                        acc[1][o] += iv1 * wv[o];
                        acc[2][o] += iv2 * wv[o];
                        acc[3][o] += iv3 * wv[o];
                    }
                }
            }
        }
        __syncthreads();
    }

#pragma unroll
    for (int d = 0; d < 4; d++) {
        int y = by0 + ybase + d;
        int xg = bx0 + pcol;
#pragma unroll
        for (int o = 0; o < 16; o++) {
            int gc = g * 16 + o;
            size_t off = (size_t)(b * 64 + gc) * HWN + y * WW + xg;
            out[off] = acc[d][o] + x[off];
        }
    }
}

// ---------------- launch ----------------
extern "C" void kernel_launch(void* const* d_in, const int* in_sizes, int n_in,
                              void* d_out, int out_size) {
    const float* x      = (const float*)d_in[0];
    const float* bridge = (const float*)d_in[1];
    const float* Wsub   = (const float*)d_in[2];
    const float* Wcb    = (const float*)d_in[3];
    float* out = (float*)d_out;

    transpose_w_kernel<<<288, 256>>>(Wsub, Wcb);
    conv1_kernel<<<dim3(8, 8, 8), 256>>>(x, bridge);
    reduce_kernel<<<dim3(NCHUNK, BB), 256>>>(bridge);
    solve_kernel<<<BB, 256>>>();
    conv2_kernel<<<dim3(16, 16, 8), 256>>>(x, out);
}

// round 3
// speedup vs baseline: 1.0941x; 1.0941x over previous
#include <cuda_runtime.h>

// Problem constants (fixed shapes)
#define BB 8
#define CC 64
#define SS 16
#define HH 256
#define WW 256
#define HWN 65536
#define NCHUNK 128          // reduction chunks per batch (512 px each)
#define PART_STRIDE 1296    // 256 gram + 1024 G + 16 r

typedef unsigned long long ull;

// ---------------- f32x2 packed-FMA helpers (Blackwell, PTX-only) ----------------
__device__ __forceinline__ void ffma2(ull& d, ull a, ull b) {
    asm("fma.rn.f32x2 %0, %1, %2, %0;" : "+l"(d) : "l"(a), "l"(b));
}
__device__ __forceinline__ ull pack2(float x, float y) {
    ull r; asm("mov.b64 %0, {%1, %2};" : "=l"(r) : "f"(x), "f"(y)); return r;
}
__device__ __forceinline__ void unpack2(float& lo, float& hi, ull v) {
    asm("mov.b64 {%0, %1}, %2;" : "=f"(lo), "=f"(hi) : "l"(v));
}

// ---------------- device scratch (no allocations allowed) ----------------
__device__ __align__(16) float g_U[BB * SS * HWN];              // conv1 output (33.5 MB)
__device__ __align__(16) float g_part[BB * NCHUNK * PART_STRIDE];
__device__ __align__(16) float g_PF2[BB * SS * CC];
__device__ __align__(16) float g_Wt_sub[128 * 9 * 16];          // [ic*9+tap][oc]
__device__ __align__(16) float g_Wt_cb[128 * 9 * 64];

// ---------------- weight pre-transpose: [oc][ic][tap] -> [ic*9+tap][oc] ----------------
__global__ void transpose_w_kernel(const float* __restrict__ Ws,
                                   const float* __restrict__ Wc) {
    int idx = blockIdx.x * 256 + threadIdx.x;
    if (idx < 16 * 1152) {
        int oc = idx / 1152; int r = idx - oc * 1152;
        g_Wt_sub[r * 16 + oc] = Ws[idx];
    }
    if (idx < 64 * 1152) {
        int oc = idx / 1152; int r = idx - oc * 1152;
        g_Wt_cb[r * 64 + oc] = Wc[idx];
    }
}

// ---------------- conv1: U = conv3x3(cat(x,bridge), W_sub), 128->16 ----------------
// tile 32x32 pixels, 256 threads, each thread: 4 rows x 1 col x 16 oc (8 f32x2 pairs)
__global__ __launch_bounds__(256, 2)
void conv1_kernel(const float* __restrict__ x, const float* __restrict__ bridge) {
    __shared__ __align__(16) float sIn[8][34][36];
    __shared__ __align__(16) float sW[8][9][16];

    int b = blockIdx.z;
    int by0 = blockIdx.y * 32, bx0 = blockIdx.x * 32;
    int tid = threadIdx.x;
    int pcol = tid & 31;
    int prow = tid >> 5;          // 0..7
    int ybase = prow * 4;

    ull acc2[4][8];
#pragma unroll
    for (int d = 0; d < 4; d++)
#pragma unroll
        for (int j = 0; j < 8; j++) acc2[d][j] = 0ull;

    for (int k = 0; k < 16; k++) {
        const float* src = (k < 8) ? x : bridge;
        int cb = (k & 7) * 8;
        // stage 8-channel input tile with halo
        for (int idx = tid; idx < 8 * 34 * 34; idx += 256) {
            int c = idx / 1156; int rem = idx - c * 1156;
            int r = rem / 34;   int cc2 = rem - r * 34;
            int gy = by0 - 1 + r, gx = bx0 - 1 + cc2;
            float v = 0.f;
            if (gy >= 0 && gy < HH && gx >= 0 && gx < WW)
                v = src[(size_t)(b * 64 + cb + c) * HWN + gy * WW + gx];
            sIn[c][r][cc2] = v;
        }
        // stage weights (contiguous chunk of pre-transposed layout)
        for (int idx = tid; idx < 1152; idx += 256)
            ((float*)sW)[idx] = g_Wt_sub[k * 1152 + idx];
        __syncthreads();

#pragma unroll
        for (int c = 0; c < 8; c++) {
#pragma unroll
            for (int ky = 0; ky < 3; ky++) {
#pragma unroll
                for (int kx = 0; kx < 3; kx++) {
                    float iv0 = sIn[c][ybase + ky + 0][pcol + kx];
                    float iv1 = sIn[c][ybase + ky + 1][pcol + kx];
                    float iv2 = sIn[c][ybase + ky + 2][pcol + kx];
                    float iv3 = sIn[c][ybase + ky + 3][pcol + kx];
                    ull ivp0 = pack2(iv0, iv0);
                    ull ivp1 = pack2(iv1, iv1);
                    ull ivp2 = pack2(iv2, iv2);
                    ull ivp3 = pack2(iv3, iv3);
                    const ulonglong2* wp =
                        reinterpret_cast<const ulonglong2*>(&sW[c][ky * 3 + kx][0]);
                    ull wv[8];
                    ulonglong2 t;
                    t = wp[0]; wv[0] = t.x; wv[1] = t.y;
                    t = wp[1]; wv[2] = t.x; wv[3] = t.y;
                    t = wp[2]; wv[4] = t.x; wv[5] = t.y;
                    t = wp[3]; wv[6] = t.x; wv[7] = t.y;
#pragma unroll
                    for (int j = 0; j < 8; j++) {
                        ffma2(acc2[0][j], ivp0, wv[j]);
                        ffma2(acc2[1][j], ivp1, wv[j]);
                        ffma2(acc2[2][j], ivp2, wv[j]);
                        ffma2(acc2[3][j], ivp3, wv[j]);
                    }
                }
            }
        }
        __syncthreads();
    }

#pragma unroll
    for (int d = 0; d < 4; d++) {
        int y = by0 + ybase + d;
        int xg = bx0 + pcol;
#pragma unroll
        for (int j = 0; j < 8; j++) {
            float lo, hi;
            unpack2(lo, hi, acc2[d][j]);
            g_U[((b * 16 + 2 * j)     << 16) + (y << 8) + xg] = lo;
            g_U[((b * 16 + 2 * j + 1) << 16) + (y << 8) + xg] = hi;
        }
    }
}

// ---------------- reduction: Gram[16,16], G[16,64], r[16] partials per 512-px chunk ----------------
__global__ __launch_bounds__(256)
void reduce_kernel(const float* __restrict__ bridge) {
    __shared__ __align__(16) float sU[16][68];
    __shared__ __align__(16) float sB[64][68];

    int b = blockIdx.y, ch = blockIdx.x;
    int tid = threadIdx.x;
    int s = tid >> 4, q = tid & 15;
    int n0 = ch * 512;

    const float* Ub = g_U + (size_t)b * 16 * HWN;
    const float* Bb = bridge + (size_t)b * 64 * HWN;

    float accG[4] = {0.f, 0.f, 0.f, 0.f};
    float accM = 0.f;
    float accR = 0.f;

    for (int sub = 0; sub < 8; sub++) {
        int n = n0 + sub * 64;
        {
            int sl = tid >> 4, p4 = (tid & 15) * 4;
            *reinterpret_cast<float4*>(&sU[sl][p4]) =
                *reinterpret_cast<const float4*>(&Ub[sl * HWN + n + p4]);
        }
#pragma unroll
        for (int r = 0; r < 4; r++) {
            int cl = (tid >> 4) + r * 16;
            int p4 = (tid & 15) * 4;
            *reinterpret_cast<float4*>(&sB[cl][p4]) =
                *reinterpret_cast<const float4*>(&Bb[cl * HWN + n + p4]);
        }
        __syncthreads();
#pragma unroll
        for (int p = 0; p < 64; p += 4) {
            float4 u  = *reinterpret_cast<float4*>(&sU[s][p]);
            float4 t4 = *reinterpret_cast<float4*>(&sU[q][p]);
            accM += u.x * t4.x + u.y * t4.y + u.z * t4.z + u.w * t4.w;
#pragma unroll
            for (int j = 0; j < 4; j++) {
                float4 bv = *reinterpret_cast<float4*>(&sB[q + j * 16][p]);
                accG[j] += u.x * bv.x + u.y * bv.y + u.z * bv.z + u.w * bv.w;
            }
            if (q == 0)
                accR += fabsf(u.x) + fabsf(u.y) + fabsf(u.z) + fabsf(u.w);
        }
        __syncthreads();
    }

    float* out = g_part + (size_t)(b * NCHUNK + ch) * PART_STRIDE;
    out[s * 16 + q] = accM;
#pragma unroll
    for (int j = 0; j < 4; j++)
        out[256 + s * 64 + q + j * 16] = accG[j];
    if (q == 0) out[1280 + s] = accR;
}

// ---------------- solve: mat = D^-1 Gram D^-1; PF2 = D^-1 mat^-1 D^-1 G ----------------
__global__ __launch_bounds__(256)
void solve_kernel() {
    __shared__ float sGram[256];
    __shared__ float sG[1024];
    __shared__ float srr[16];
    __shared__ double A[16][17];
    __shared__ double M[16][17];
    __shared__ double spiv;

    int b = blockIdx.x;
    int tid = threadIdx.x;
    const float* base = g_part + (size_t)b * NCHUNK * PART_STRIDE;

    {
        float a = 0.f;
        for (int ch = 0; ch < NCHUNK; ch++) a += base[ch * PART_STRIDE + tid];
        sGram[tid] = a;
    }
#pragma unroll
    for (int j = 0; j < 4; j++) {
        int e = tid + j * 256;
        float a = 0.f;
        for (int ch = 0; ch < NCHUNK; ch++) a += base[ch * PART_STRIDE + 256 + e];
        sG[e] = a;
    }
    if (tid < 16) {
        float a = 0.f;
        for (int ch = 0; ch < NCHUNK; ch++) a += base[ch * PART_STRIDE + 1280 + tid];
        srr[tid] = 1e-6f + a;
    }
    __syncthreads();

    {
        int i = tid >> 4, t = tid & 15;
        A[i][t] = (double)sGram[tid] / ((double)srr[i] * (double)srr[t]);
        M[i][t] = (i == t) ? 1.0 : 0.0;
    }
    __syncthreads();

    // Gauss-Jordan (SPD, no pivoting), parallel over 256 threads
    for (int k = 0; k < 16; k++) {
        if (tid == 0) spiv = 1.0 / A[k][k];
        __syncthreads();
        if (tid < 16) { A[k][tid] *= spiv; M[k][tid] *= spiv; }
        __syncthreads();
        int i = tid >> 4, t = tid & 15;
        double f = A[i][k];
        __syncthreads();
        if (i != k) {
            A[i][t] -= f * A[k][t];
            M[i][t] -= f * M[k][t];
        }
        __syncthreads();
    }

#pragma unroll
    for (int j = 0; j < 4; j++) {
        int e = tid + j * 256;
        int s = e >> 6, c = e & 63;
        double v = 0.0;
#pragma unroll
        for (int t = 0; t < 16; t++)
            v += M[s][t] * ((double)sG[t * 64 + c] / (double)srr[t]);
        g_PF2[b * 1024 + e] = (float)(v / (double)srr[s]);
    }
}

// ---------------- conv2 (fused): out = conv3x3(cat(x, U^T*PF2), W_cb) + x ----------------
// tile 16x16 pixels, 256 threads = 4 oc-groups x 64 pixel-slots (4 rows each)
__global__ __launch_bounds__(256, 2)
void conv2_kernel(const float* __restrict__ x, float* __restrict__ out) {
    __shared__ float sU[16][18][20];
    __shared__ float sInC[4][18][20];
    __shared__ __align__(16) float sWC[4][9][64];
    __shared__ float sPF[1024];

    int b = blockIdx.z;
    int by0 = blockIdx.y * 16, bx0 = blockIdx.x * 16;
    int tid = threadIdx.x;
    int pcol = tid & 15;
    int prow = (tid >> 4) & 3;
    int g = tid >> 6;             // oc group 0..3
    int ybase = prow * 4;

    for (int idx = tid; idx < 1024; idx += 256) sPF[idx] = g_PF2[b * 1024 + idx];
    for (int idx = tid; idx < 16 * 324; idx += 256) {
        int s2 = idx / 324; int rem = idx - s2 * 324;
        int r = rem / 18;   int cc2 = rem - r * 18;
        int gy = by0 - 1 + r, gx = bx0 - 1 + cc2;
        float v = 0.f;
        if (gy >= 0 && gy < HH && gx >= 0 && gx < WW)
            v = g_U[((b * 16 + s2) << 16) + (gy << 8) + gx];
        sU[s2][r][cc2] = v;
    }

    ull acc2[4][8];
#pragma unroll
    for (int d = 0; d < 4; d++)
#pragma unroll
        for (int j = 0; j < 8; j++) acc2[d][j] = 0ull;
    __syncthreads();

    for (int k = 0; k < 32; k++) {
        // weights: contiguous chunk
        for (int idx = tid; idx < 2304; idx += 256)
            ((float*)sWC)[idx] = g_Wt_cb[k * 2304 + idx];
        if (k < 16) {
            int cb = k * 4;
            for (int idx = tid; idx < 4 * 324; idx += 256) {
                int c = idx / 324; int rem = idx - c * 324;
                int r = rem / 18;  int cc2 = rem - r * 18;
                int gy = by0 - 1 + r, gx = bx0 - 1 + cc2;
                float v = 0.f;
                if (gy >= 0 && gy < HH && gx >= 0 && gx < WW)
                    v = x[(size_t)(b * 64 + cb + c) * HWN + gy * WW + gx];
                sInC[c][r][cc2] = v;
            }
        } else {
            int cpb = (k - 16) * 4;  // projected-channel base
            for (int idx = tid; idx < 4 * 324; idx += 256) {
                int c = idx / 324; int rem = idx - c * 324;
                int r = rem / 18;  int cc2 = rem - r * 18;
                float v = 0.f;
#pragma unroll
                for (int s2 = 0; s2 < 16; s2++)
                    v += sU[s2][r][cc2] * sPF[s2 * 64 + cpb + c];
                sInC[c][r][cc2] = v;
            }
        }
        __syncthreads();

#pragma unroll
        for (int c = 0; c < 4; c++) {
#pragma unroll
            for (int ky = 0; ky < 3; ky++) {
#pragma unroll
                for (int kx = 0; kx < 3; kx++) {
                    float iv0 = sInC[c][ybase + ky + 0][pcol + kx];
                    float iv1 = sInC[c][ybase + ky + 1][pcol + kx];
                    float iv2 = sInC[c][ybase + ky + 2][pcol + kx];
                    float iv3 = sInC[c][ybase + ky + 3][pcol + kx];
                    ull ivp0 = pack2(iv0, iv0);
                    ull ivp1 = pack2(iv1, iv1);
                    ull ivp2 = pack2(iv2, iv2);
                    ull ivp3 = pack2(iv3, iv3);
                    const ulonglong2* wp =
                        reinterpret_cast<const ulonglong2*>(&sWC[c][ky * 3 + kx][g * 16]);
                    ull wv[8];
                    ulonglong2 t;
                    t = wp[0]; wv[0] = t.x; wv[1] = t.y;
                    t = wp[1]; wv[2] = t.x; wv[3] = t.y;
                    t = wp[2]; wv[4] = t.x; wv[5] = t.y;
                    t = wp[3]; wv[6] = t.x; wv[7] = t.y;
#pragma unroll
                    for (int j = 0; j < 8; j++) {
                        ffma2(acc2[0][j], ivp0, wv[j]);
                        ffma2(acc2[1][j], ivp1, wv[j]);
                        ffma2(acc2[2][j], ivp2, wv[j]);
                        ffma2(acc2[3][j], ivp3, wv[j]);
                    }
                }
            }
        }
        __syncthreads();
    }

#pragma unroll
    for (int d = 0; d < 4; d++) {
        int y = by0 + ybase + d;
        int xg = bx0 + pcol;
#pragma unroll
        for (int j = 0; j < 8; j++) {
            float lo, hi;
            unpack2(lo, hi, acc2[d][j]);
            int gc0 = g * 16 + 2 * j;
            size_t off0 = (size_t)(b * 64 + gc0) * HWN + y * WW + xg;
            size_t off1 = off0 + HWN;
            out[off0] = lo + x[off0];
            out[off1] = hi + x[off1];
        }
    }
}

// ---------------- launch ----------------
extern "C" void kernel_launch(void* const* d_in, const int* in_sizes, int n_in,
                              void* d_out, int out_size) {
    const float* x      = (const float*)d_in[0];
    const float* bridge = (const float*)d_in[1];
    const float* Wsub   = (const float*)d_in[2];
    const float* Wcb    = (const float*)d_in[3];
    float* out = (float*)d_out;

    transpose_w_kernel<<<288, 256>>>(Wsub, Wcb);
    conv1_kernel<<<dim3(8, 8, 8), 256>>>(x, bridge);
    reduce_kernel<<<dim3(NCHUNK, BB), 256>>>(bridge);
    solve_kernel<<<BB, 256>>>();
    conv2_kernel<<<dim3(16, 16, 8), 256>>>(x, out);
}

// round 5
// speedup vs baseline: 1.9331x; 1.7668x over previous
#include <cuda_runtime.h>
#include <cuda_bf16.h>
#include <cstdint>

#define BB 8
#define HWN 65536
#define NCHUNK 128
#define PART_STRIDE 1296

typedef uint32_t u32;

// ================= device scratch =================
// NHWC bf16 planes: [v(hi/lo)][cg(0:x,1:bridge)][b][pixel][64ch]
__device__ __align__(16) __nv_bfloat16 g_in[(size_t)4 * 8 * HWN * 64];
#define PLANE(v, cg, b) (((size_t)(((v) * 2 + (cg)) * 8 + (b))) << 22)
__device__ __align__(16) float g_U[(size_t)BB * 16 * HWN];
__device__ __align__(16) __nv_bfloat16 g_Uh[(size_t)BB * HWN * 16];
__device__ __align__(16) __nv_bfloat16 g_Ul[(size_t)BB * HWN * 16];
__device__ __align__(16) float g_part[BB * NCHUNK * PART_STRIDE];
__device__ __align__(16) float g_PF2[BB * 16 * 64];
// pre-swizzled weights: conv1 [wv][tap][16oc][128ch], conv2-x [wv][tap][64oc][64ch]
__device__ __align__(16) unsigned char g_Wc1[73728];
__device__ __align__(16) unsigned char g_Wc2[147456];
// per-batch folded proj weights [b][wv][tap][64oc][16s]
__device__ __align__(16) __nv_bfloat16 g_W2[(size_t)BB * 18432];

// ================= helpers =================
__device__ __forceinline__ u32 smem_u32(const void* p) {
    u32 a;
    asm("{ .reg .u64 t; cvta.to.shared.u64 t, %1; cvt.u32.u64 %0, t; }" : "=r"(a) : "l"(p));
    return a;
}
__device__ __forceinline__ void ldm4(u32* r, u32 a) {
    asm volatile("ldmatrix.sync.aligned.m8n8.x4.shared.b16 {%0,%1,%2,%3}, [%4];"
                 : "=r"(r[0]), "=r"(r[1]), "=r"(r[2]), "=r"(r[3]) : "r"(a));
}
__device__ __forceinline__ void mma16816(float* c, const u32* a, const u32* b) {
    asm volatile("mma.sync.aligned.m16n8k16.row.col.f32.bf16.bf16.f32 "
                 "{%0,%1,%2,%3}, {%4,%5,%6,%7}, {%8,%9}, {%0,%1,%2,%3};"
                 : "+f"(c[0]), "+f"(c[1]), "+f"(c[2]), "+f"(c[3])
                 : "r"(a[0]), "r"(a[1]), "r"(a[2]), "r"(a[3]), "r"(b[0]), "r"(b[1]));
}
__device__ __forceinline__ void split(float f, __nv_bfloat16& h, __nv_bfloat16& l) {
    h = __float2bfloat16(f);
    l = __float2bfloat16(f - __bfloat162float(h));
}

// ================= weight prep =================
__global__ void prep_w_kernel(const float* __restrict__ Ws, const float* __restrict__ Wc) {
    int id = blockIdx.x * 256 + threadIdx.x;
    if (id < 64 * 1152) {
        int oc = id / 1152, rem = id - oc * 1152, ic = rem / 9, tap = rem - ic * 9;
        if (ic < 64) {
            __nv_bfloat16 h, l;
            split(Wc[id], h, l);
            u32 off = (u32)((tap * 64 + oc) * 128) + (u32)((ic * 2) ^ ((oc & 7) << 4));
            *(__nv_bfloat16*)(g_Wc2 + off) = h;
            *(__nv_bfloat16*)(g_Wc2 + off + 73728) = l;
        }
    }
    if (id < 16 * 1152) {
        int oc = id / 1152, rem = id - oc * 1152, ic = rem / 9, tap = rem - ic * 9;
        __nv_bfloat16 h, l;
        split(Ws[id], h, l);
        u32 off = (u32)((tap * 16 + oc) * 256) + (u32)((ic * 2) ^ ((oc & 7) << 4));
        *(__nv_bfloat16*)(g_Wc1 + off) = h;
        *(__nv_bfloat16*)(g_Wc1 + off + 36864) = l;
    }
}

// ================= NCHW fp32 -> NHWC bf16 hi/lo =================
__global__ __launch_bounds__(256)
void convert_kernel(const float* __restrict__ x, const float* __restrict__ bridge) {
    __shared__ float sT[64][68];
    int b = blockIdx.z, cg = blockIdx.y, pb = blockIdx.x;
    const float* src = cg ? bridge : x;
    int tid = threadIdx.x;
    int p0 = pb * 64;
    for (int i = tid; i < 64 * 64; i += 256) {
        int c = i >> 6, px = i & 63;
        sT[c][px] = src[((size_t)(b * 64 + c) << 16) + p0 + px];
    }
    __syncthreads();
    for (int i = tid; i < 512; i += 256) {
        int px = i >> 3, c8 = i & 7;
        __nv_bfloat16 hb[8], lb[8];
#pragma unroll
        for (int j = 0; j < 8; j++)
            split(sT[c8 * 8 + j][px], hb[j], lb[j]);
        size_t base = ((size_t)(p0 + px) << 6) + c8 * 8;
        *(uint4*)&g_in[PLANE(0, cg, b) + base] = *(uint4*)hb;
        *(uint4*)&g_in[PLANE(1, cg, b) + base] = *(uint4*)lb;
    }
}

// ================= conv1: mma.sync, 128->16ch, writes U fp32 + bf16 hi/lo =================
__global__ __launch_bounds__(256, 1)
void conv1_kernel() {
    extern __shared__ __align__(16) unsigned char sm[];
    const u32 AOF = 73728;   // 4 A-tiles [xh,xl,bh,bl] of 16640B
    u32 sb = smem_u32(sm);
    int tid = threadIdx.x, lane = tid & 31, wid = tid >> 5;
    int b = blockIdx.z, y0 = blockIdx.y * 4, x0 = blockIdx.x * 128;

    for (int i = tid; i < 73728 / 16; i += 256)
        ((uint4*)sm)[i] = ((const uint4*)g_Wc1)[i];

    int i8 = lane & 7;
    int a_mh = (lane >> 3) & 1, a_kh = lane >> 4;
    int b_kh = (lane >> 3) & 1, b_nh = lane >> 4;
    int pxw = wid * 16 + a_mh * 8 + i8;
    int ocw = b_nh * 8 + i8;
    u32 rowOff[3], swv[3];
#pragma unroll
    for (int kx = 0; kx < 3; kx++) {
        int p = pxw + kx;
        rowOff[kx] = p * 128;
        swv[kx] = (u32)((p & 7) << 4);
    }
    u32 bRow = ocw * 256, bSw = (u32)((ocw & 7) << 4);
    int g = lane >> 2, t4 = lane & 3;

    for (int y = 0; y < 4; y++) {
        int yy = y0 + y;
        float acc[2][4];
#pragma unroll
        for (int j = 0; j < 2; j++)
#pragma unroll
            for (int q = 0; q < 4; q++) acc[j][q] = 0.f;

        for (int ky = 0; ky < 3; ky++) {
            int ys = yy + ky - 1;
            bool yok = (unsigned)ys < 256u;
            __syncthreads();
            for (int i = tid; i < 4160; i += 256) {
                int t = i / 1040, j = i - t * 1040;
                int px = j >> 3, c8 = j & 7;
                int xs = x0 + px - 1;
                uint4 v = make_uint4(0, 0, 0, 0);
                if (yok && (unsigned)xs < 256u)
                    v = *(const uint4*)&g_in[PLANE(t & 1, t >> 1, b) +
                                             (((size_t)ys * 256 + xs) << 6) + c8 * 8];
                *(uint4*)(sm + AOF + t * 16640 + px * 128 +
                          ((u32)(c8 * 16) ^ ((u32)(px & 7) << 4))) = v;
            }
            __syncthreads();
#pragma unroll
            for (int kx = 0; kx < 3; kx++) {
                int tap = ky * 3 + kx;
                u32 wbase = (u32)(tap * 4096) + bRow;
#pragma unroll
                for (int kc = 0; kc < 8; kc++) {
                    u32 kb = (u32)((kc & 3) * 32 + a_kh * 16);
                    u32 aHi = sb + AOF + (u32)((kc >> 2) * 2 * 16640) + rowOff[kx] +
                              (kb ^ swv[kx]);
                    u32 Ah[4], Al[4], BH[4], BL[4];
                    ldm4(Ah, aHi);
                    ldm4(Al, aHi + 16640);
                    u32 bA = sb + wbase + ((u32)(kc * 32 + b_kh * 16) ^ bSw);
                    ldm4(BH, bA);
                    ldm4(BL, bA + 36864);
#pragma unroll
                    for (int j = 0; j < 2; j++) {
                        mma16816(acc[j], Ah, BH + 2 * j);
                        mma16816(acc[j], Al, BH + 2 * j);
                        mma16816(acc[j], Ah, BL + 2 * j);
                    }
                }
            }
        }
        // writeout: fp32 U + bf16 hi/lo U
        size_t rowb = (size_t)yy * 256;
        int px0 = x0 + wid * 16 + g;
#pragma unroll
        for (int j = 0; j < 2; j++) {
            int oc = j * 8 + 2 * t4;
            g_U[((size_t)(b * 16 + oc) << 16) + rowb + px0]         = acc[j][0];
            g_U[((size_t)(b * 16 + oc + 1) << 16) + rowb + px0]     = acc[j][1];
            g_U[((size_t)(b * 16 + oc) << 16) + rowb + px0 + 8]     = acc[j][2];
            g_U[((size_t)(b * 16 + oc + 1) << 16) + rowb + px0 + 8] = acc[j][3];
#pragma unroll
            for (int h2 = 0; h2 < 2; h2++) {
                int px = px0 + h2 * 8;
                __nv_bfloat16 h0, l0, h1, l1;
                split(acc[j][h2 * 2 + 0], h0, l0);
                split(acc[j][h2 * 2 + 1], h1, l1);
                size_t idx = ((size_t)b * HWN + rowb + px) * 16 + oc;
                __nv_bfloat162 hh, ll;
                hh.x = h0; hh.y = h1;
                ll.x = l0; ll.y = l1;
                *(__nv_bfloat162*)&g_Uh[idx] = hh;
                *(__nv_bfloat162*)&g_Ul[idx] = ll;
            }
        }
    }
}

// ================= reduction (fp32, unchanged) =================
__global__ __launch_bounds__(256)
void reduce_kernel(const float* __restrict__ bridge) {
    __shared__ __align__(16) float sU[16][68];
    __shared__ __align__(16) float sB[64][68];
    int b = blockIdx.y, ch = blockIdx.x;
    int tid = threadIdx.x;
    int s = tid >> 4, q = tid & 15;
    int n0 = ch * 512;
    const float* Ub = g_U + (size_t)b * 16 * HWN;
    const float* Bb = bridge + (size_t)b * 64 * HWN;
    float accG[4] = {0.f, 0.f, 0.f, 0.f};
    float accM = 0.f, accR = 0.f;
    for (int sub = 0; sub < 8; sub++) {
        int n = n0 + sub * 64;
        {
            int sl = tid >> 4, p4 = (tid & 15) * 4;
            *reinterpret_cast<float4*>(&sU[sl][p4]) =
                *reinterpret_cast<const float4*>(&Ub[sl * HWN + n + p4]);
        }
#pragma unroll
        for (int r = 0; r < 4; r++) {
            int cl = (tid >> 4) + r * 16;
            int p4 = (tid & 15) * 4;
            *reinterpret_cast<float4*>(&sB[cl][p4]) =
                *reinterpret_cast<const float4*>(&Bb[cl * HWN + n + p4]);
        }
        __syncthreads();
#pragma unroll
        for (int p = 0; p < 64; p += 4) {
            float4 u = *reinterpret_cast<float4*>(&sU[s][p]);
            float4 t4 = *reinterpret_cast<float4*>(&sU[q][p]);
            accM += u.x * t4.x + u.y * t4.y + u.z * t4.z + u.w * t4.w;
#pragma unroll
            for (int j = 0; j < 4; j++) {
                float4 bv = *reinterpret_cast<float4*>(&sB[q + j * 16][p]);
                accG[j] += u.x * bv.x + u.y * bv.y + u.z * bv.z + u.w * bv.w;
            }
            if (q == 0) accR += fabsf(u.x) + fabsf(u.y) + fabsf(u.z) + fabsf(u.w);
        }
        __syncthreads();
    }
    float* o = g_part + (size_t)(b * NCHUNK + ch) * PART_STRIDE;
    o[s * 16 + q] = accM;
#pragma unroll
    for (int j = 0; j < 4; j++) o[256 + s * 64 + q + j * 16] = accG[j];
    if (q == 0) o[1280 + s] = accR;
}

// ================= solve (unchanged) =================
__global__ __launch_bounds__(256)
void solve_kernel() {
    __shared__ float sGram[256];
    __shared__ float sG[1024];
    __shared__ float srr[16];
    __shared__ double A[16][17];
    __shared__ double M[16][17];
    __shared__ double spiv;
    int b = blockIdx.x;
    int tid = threadIdx.x;
    const float* base = g_part + (size_t)b * NCHUNK * PART_STRIDE;
    {
        float a = 0.f;
        for (int ch = 0; ch < NCHUNK; ch++) a += base[ch * PART_STRIDE + tid];
        sGram[tid] = a;
    }
#pragma unroll
    for (int j = 0; j < 4; j++) {
        int e = tid + j * 256;
        float a = 0.f;
        for (int ch = 0; ch < NCHUNK; ch++) a += base[ch * PART_STRIDE + 256 + e];
        sG[e] = a;
    }
    if (tid < 16) {
        float a = 0.f;
        for (int ch = 0; ch < NCHUNK; ch++) a += base[ch * PART_STRIDE + 1280 + tid];
        srr[tid] = 1e-6f + a;
    }
    __syncthreads();
    {
        int i = tid >> 4, t = tid & 15;
        A[i][t] = (double)sGram[tid] / ((double)srr[i] * (double)srr[t]);
        M[i][t] = (i == t) ? 1.0 : 0.0;
    }
    __syncthreads();
    for (int k = 0; k < 16; k++) {
        if (tid == 0) spiv = 1.0 / A[k][k];
        __syncthreads();
        if (tid < 16) { A[k][tid] *= spiv; M[k][tid] *= spiv; }
        __syncthreads();
        int i = tid >> 4, t = tid & 15;
        double f = A[i][k];
        __syncthreads();
        if (i != k) { A[i][t] -= f * A[k][t]; M[i][t] -= f * M[k][t]; }
        __syncthreads();
    }
#pragma unroll
    for (int j = 0; j < 4; j++) {
        int e = tid + j * 256;
        int s = e >> 6, c = e & 63;
        double v = 0.0;
#pragma unroll
        for (int t = 0; t < 16; t++)
            v += M[s][t] * ((double)sG[t * 64 + c] / (double)srr[t]);
        g_PF2[b * 1024 + e] = (float)(v / (double)srr[s]);
    }
}

// ================= fold PF2 into conv2 proj-weights =================
__global__ __launch_bounds__(256)
void w2eff_kernel(const float* __restrict__ Wc) {
    __shared__ float sPF[1024];
    int b = blockIdx.x, tid = threadIdx.x;
    for (int i = tid; i < 1024; i += 256) sPF[i] = g_PF2[b * 1024 + i];
    __syncthreads();
    for (int e = tid; e < 9216; e += 256) {
        int tap = e / 1024, r = e & 1023, o = r >> 4, s = r & 15;
        float v = 0.f;
#pragma unroll
        for (int c = 0; c < 64; c++)
            v += Wc[o * 1152 + (64 + c) * 9 + tap] * sPF[s * 64 + c];
        __nv_bfloat16 h, l;
        split(v, h, l);
        g_W2[(size_t)b * 18432 + (size_t)(tap * 1024 + o * 16 + s)] = h;
        g_W2[(size_t)b * 18432 + (size_t)(9216 + tap * 1024 + o * 16 + s)] = l;
    }
}

// ================= conv2: mma.sync, (64 x-ch + 16 U-ch) -> 64ch, + residual =================
__global__ __launch_bounds__(256, 1)
void conv2_kernel(const float* __restrict__ x, float* __restrict__ out) {
    extern __shared__ __align__(16) unsigned char sm[];
    const u32 WU = 147456, AX = 184320, AU = 217600;
    u32 sb = smem_u32(sm);
    int tid = threadIdx.x, lane = tid & 31, wid = tid >> 5;
    int b = blockIdx.z, y0 = blockIdx.y * 4, x0 = blockIdx.x * 128;

    for (int i = tid; i < 147456 / 16; i += 256)
        ((uint4*)sm)[i] = ((const uint4*)g_Wc2)[i];
    for (int i = tid; i < 36864 / 16; i += 256)
        ((uint4*)(sm + WU))[i] = ((const uint4*)(g_W2 + (size_t)b * 18432))[i];

    int i8 = lane & 7;
    int a_mh = (lane >> 3) & 1, a_kh = lane >> 4;
    int b_kh = (lane >> 3) & 1, b_nh = lane >> 4;
    int wm = wid & 3, wn = wid >> 2;
    int pxw = wm * 32 + a_mh * 8 + i8;
    int ocw = wn * 32 + b_nh * 8 + i8;
    u32 rowOff[3], swv[3], rowU[3];
#pragma unroll
    for (int kx = 0; kx < 3; kx++) {
        int p = pxw + kx;
        rowOff[kx] = p * 128;
        swv[kx] = (u32)((p & 7) << 4);
        rowU[kx] = p * 32;
    }
    u32 bRow = ocw * 128, bSw = (u32)((ocw & 7) << 4);
    u32 bRowU = ocw * 32;
    int g = lane >> 2, t4 = lane & 3;

    for (int y = 0; y < 4; y++) {
        int yy = y0 + y;
        float acc[2][4][4];
#pragma unroll
        for (int m = 0; m < 2; m++)
#pragma unroll
            for (int j = 0; j < 4; j++)
#pragma unroll
                for (int q = 0; q < 4; q++) acc[m][j][q] = 0.f;

        for (int ky = 0; ky < 3; ky++) {
            int ys = yy + ky - 1;
            bool yok = (unsigned)ys < 256u;
            __syncthreads();
            for (int i = tid; i < 2080; i += 256) {
                int var = i >= 1040;
                int j = var ? i - 1040 : i;
                int px = j >> 3, c8 = j & 7;
                int xs = x0 + px - 1;
                uint4 v = make_uint4(0, 0, 0, 0);
                if (yok && (unsigned)xs < 256u)
                    v = *(const uint4*)&g_in[PLANE(var, 0, b) +
                                             (((size_t)ys * 256 + xs) << 6) + c8 * 8];
                *(uint4*)(sm + AX + var * 16640 + px * 128 +
                          ((u32)(c8 * 16) ^ ((u32)(px & 7) << 4))) = v;
            }
            for (int i = tid; i < 520; i += 256) {
                int var = i >= 260;
                int j = var ? i - 260 : i;
                int px = j >> 1, hf = j & 1;
                int xs = x0 + px - 1;
                uint4 v = make_uint4(0, 0, 0, 0);
                if (yok && (unsigned)xs < 256u) {
                    const __nv_bfloat16* src = var ? g_Ul : g_Uh;
                    v = *(const uint4*)&src[((size_t)b * HWN + (size_t)ys * 256 + xs) * 16 +
                                            hf * 8];
                }
                *(uint4*)(sm + AU + var * 4160 + px * 32 + hf * 16) = v;
            }
            __syncthreads();
#pragma unroll
            for (int kx = 0; kx < 3; kx++) {
                int tap = ky * 3 + kx;
#pragma unroll
                for (int kc = 0; kc < 4; kc++) {
                    u32 kb = (u32)(kc * 32 + a_kh * 16);
                    u32 aHi = sb + AX + rowOff[kx] + (kb ^ swv[kx]);
                    u32 A0h[4], A1h[4], A0l[4], A1l[4];
                    ldm4(A0h, aHi);
                    ldm4(A1h, aHi + 2048);
                    ldm4(A0l, aHi + 16640);
                    ldm4(A1l, aHi + 16640 + 2048);
                    u32 bA = sb + (u32)(tap * 8192) + bRow +
                             ((u32)(kc * 32 + b_kh * 16) ^ bSw);
                    u32 BH[8], BL[8];
                    ldm4(BH, bA);
                    ldm4(BH + 4, bA + 2048);
                    ldm4(BL, bA + 73728);
                    ldm4(BL + 4, bA + 73728 + 2048);
#pragma unroll
                    for (int j = 0; j < 4; j++) {
                        mma16816(acc[0][j], A0h, BH + 2 * j);
                        mma16816(acc[1][j], A1h, BH + 2 * j);
                        mma16816(acc[0][j], A0l, BH + 2 * j);
                        mma16816(acc[1][j], A1l, BH + 2 * j);
                        mma16816(acc[0][j], A0h, BL + 2 * j);
                        mma16816(acc[1][j], A1h, BL + 2 * j);
                    }
                }
                // U part (single k16 of 16 subspace channels)
                {
                    u32 aHi = sb + AU + rowU[kx] + (u32)(a_kh * 16);
                    u32 A0h[4], A1h[4], A0l[4], A1l[4];
                    ldm4(A0h, aHi);
                    ldm4(A1h, aHi + 512);
                    ldm4(A0l, aHi + 4160);
                    ldm4(A1l, aHi + 4160 + 512);
                    u32 bA = sb + WU + (u32)(tap * 2048) + bRowU + (u32)(b_kh * 16);
                    u32 BH[8], BL[8];
                    ldm4(BH, bA);
                    ldm4(BH + 4, bA + 512);
                    ldm4(BL, bA + 18432);
                    ldm4(BL + 4, bA + 18432 + 512);
#pragma unroll
                    for (int j = 0; j < 4; j++) {
                        mma16816(acc[0][j], A0h, BH + 2 * j);
                        mma16816(acc[1][j], A1h, BH + 2 * j);
                        mma16816(acc[0][j], A0l, BH + 2 * j);
                        mma16816(acc[1][j], A1l, BH + 2 * j);
                        mma16816(acc[0][j], A0h, BL + 2 * j);
                        mma16816(acc[1][j], A1h, BL + 2 * j);
                    }
                }
            }
        }
        // writeout + residual
        size_t rowb = (size_t)yy * 256;
        int px0 = x0 + wm * 32 + g;
#pragma unroll
        for (int m = 0; m < 2; m++) {
#pragma unroll
            for (int j = 0; j < 4; j++) {
                int oc = wn * 32 + j * 8 + 2 * t4;
                int px = px0 + m * 16;
                size_t o0 = ((size_t)(b * 64 + oc) << 16) + rowb + px;
                size_t o1 = o0 + HWN;
                out[o0] = acc[m][j][0] + x[o0];
                out[o1] = acc[m][j][1] + x[o1];
                out[o0 + 8] = acc[m][j][2] + x[o0 + 8];
                out[o1 + 8] = acc[m][j][3] + x[o1 + 8];
            }
        }
    }
}

// ================= launch =================
extern "C" void kernel_launch(void* const* d_in, const int* in_sizes, int n_in,
                              void* d_out, int out_size) {
    const float* x      = (const float*)d_in[0];
    const float* bridge = (const float*)d_in[1];
    const float* Wsub   = (const float*)d_in[2];
    const float* Wcb    = (const float*)d_in[3];
    float* out = (float*)d_out;

    cudaFuncSetAttribute(conv1_kernel, cudaFuncAttributeMaxDynamicSharedMemorySize, 140288);
    cudaFuncSetAttribute(conv2_kernel, cudaFuncAttributeMaxDynamicSharedMemorySize, 225920);

    prep_w_kernel<<<288, 256>>>(Wsub, Wcb);
    convert_kernel<<<dim3(1024, 2, 8), 256>>>(x, bridge);
    conv1_kernel<<<dim3(2, 64, 8), 256, 140288>>>();
    reduce_kernel<<<dim3(NCHUNK, BB), 256>>>(bridge);
    solve_kernel<<<BB, 256>>>();
    w2eff_kernel<<<BB, 256>>>(Wcb);
    conv2_kernel<<<dim3(2, 64, 8), 256, 225920>>>(x, out);
}

// round 6
// speedup vs baseline: 2.1988x; 1.1374x over previous
#include <cuda_runtime.h>
#include <cuda_bf16.h>
#include <cstdint>

#define BB 8
#define HWN 65536
#define NCHUNK 128
#define PART_STRIDE 1296

typedef uint32_t u32;

// ================= device scratch =================
__device__ __align__(16) __nv_bfloat16 g_in[(size_t)4 * 8 * HWN * 64];
#define PLANE(v, cg, b) (((size_t)(((v) * 2 + (cg)) * 8 + (b))) << 22)
__device__ __align__(16) float g_U[(size_t)BB * 16 * HWN];
__device__ __align__(16) __nv_bfloat16 g_Uh[(size_t)BB * HWN * 16];
__device__ __align__(16) __nv_bfloat16 g_Ul[(size_t)BB * HWN * 16];
__device__ __align__(16) float g_part[BB * NCHUNK * PART_STRIDE];
__device__ __align__(16) float g_PF2[BB * 16 * 64];
__device__ __align__(16) unsigned char g_Wc1[73728];
__device__ __align__(16) unsigned char g_Wc2[147456];
__device__ __align__(16) __nv_bfloat16 g_W2[(size_t)BB * 18432];

// ================= helpers =================
__device__ __forceinline__ u32 smem_u32(const void* p) {
    u32 a;
    asm("{ .reg .u64 t; cvta.to.shared.u64 t, %1; cvt.u32.u64 %0, t; }" : "=r"(a) : "l"(p));
    return a;
}
__device__ __forceinline__ void ldm4(u32* r, u32 a) {
    asm volatile("ldmatrix.sync.aligned.m8n8.x4.shared.b16 {%0,%1,%2,%3}, [%4];"
                 : "=r"(r[0]), "=r"(r[1]), "=r"(r[2]), "=r"(r[3]) : "r"(a));
}
__device__ __forceinline__ void mma16816(float* c, const u32* a, const u32* b) {
    asm volatile("mma.sync.aligned.m16n8k16.row.col.f32.bf16.bf16.f32 "
                 "{%0,%1,%2,%3}, {%4,%5,%6,%7}, {%8,%9}, {%0,%1,%2,%3};"
                 : "+f"(c[0]), "+f"(c[1]), "+f"(c[2]), "+f"(c[3])
                 : "r"(a[0]), "r"(a[1]), "r"(a[2]), "r"(a[3]), "r"(b[0]), "r"(b[1]));
}
__device__ __forceinline__ void split(float f, __nv_bfloat16& h, __nv_bfloat16& l) {
    h = __float2bfloat16(f);
    l = __float2bfloat16(f - __bfloat162float(h));
}
__device__ __forceinline__ void cpa16(u32 dst, const void* src, bool pred) {
    unsigned sz = pred ? 16u : 0u;
    asm volatile("cp.async.cg.shared.global [%0], [%1], 16, %2;"
                 :: "r"(dst), "l"(__cvta_generic_to_global(src)), "r"(sz));
}
#define CP_COMMIT() asm volatile("cp.async.commit_group;" ::: "memory")
#define CP_WAIT0()  asm volatile("cp.async.wait_group 0;" ::: "memory")

// ================= weight prep =================
__global__ void prep_w_kernel(const float* __restrict__ Ws, const float* __restrict__ Wc) {
    int id = blockIdx.x * 256 + threadIdx.x;
    if (id < 64 * 1152) {
        int oc = id / 1152, rem = id - oc * 1152, ic = rem / 9, tap = rem - ic * 9;
        if (ic < 64) {
            __nv_bfloat16 h, l;
            split(Wc[id], h, l);
            u32 off = (u32)((tap * 64 + oc) * 128) + (u32)((ic * 2) ^ ((oc & 7) << 4));
            *(__nv_bfloat16*)(g_Wc2 + off) = h;
            *(__nv_bfloat16*)(g_Wc2 + off + 73728) = l;
        }
    }
    if (id < 16 * 1152) {
        int oc = id / 1152, rem = id - oc * 1152, ic = rem / 9, tap = rem - ic * 9;
        __nv_bfloat16 h, l;
        split(Ws[id], h, l);
        u32 off = (u32)((tap * 16 + oc) * 256) + (u32)((ic * 2) ^ ((oc & 7) << 4));
        *(__nv_bfloat16*)(g_Wc1 + off) = h;
        *(__nv_bfloat16*)(g_Wc1 + off + 36864) = l;
    }
}

// ================= NCHW fp32 -> NHWC bf16 hi/lo =================
__global__ __launch_bounds__(256)
void convert_kernel(const float* __restrict__ x, const float* __restrict__ bridge) {
    __shared__ float sT[64][68];
    int b = blockIdx.z, cg = blockIdx.y, pb = blockIdx.x;
    const float* src = cg ? bridge : x;
    int tid = threadIdx.x;
    int p0 = pb * 64;
    for (int i = tid; i < 64 * 64; i += 256) {
        int c = i >> 6, px = i & 63;
        sT[c][px] = src[((size_t)(b * 64 + c) << 16) + p0 + px];
    }
    __syncthreads();
    for (int i = tid; i < 512; i += 256) {
        int px = i >> 3, c8 = i & 7;
        __nv_bfloat16 hb[8], lb[8];
#pragma unroll
        for (int j = 0; j < 8; j++)
            split(sT[c8 * 8 + j][px], hb[j], lb[j]);
        size_t base = ((size_t)(p0 + px) << 6) + c8 * 8;
        *(uint4*)&g_in[PLANE(0, cg, b) + base] = *(uint4*)hb;
        *(uint4*)&g_in[PLANE(1, cg, b) + base] = *(uint4*)lb;
    }
}

// ================= conv1: strip 64px x 32y, 4-slot row rotation =================
#define C1_SLOT0 73728
#define C1_SLOTSZ 33792

__device__ __forceinline__ void c1_stage(u32 sb, int b, int x0, int ys, u32 slot, int tid) {
    bool yok = (unsigned)ys < 256u;
    int ysc = yok ? ys : 0;
    for (int i = tid; i < 2112; i += 256) {
        int p = i / 528, j = i - p * 528;
        int px = j >> 3, c8 = j & 7;
        int gx = x0 - 1 + px;
        bool ok = yok && (unsigned)gx < 256u;
        int gxc = ((unsigned)gx < 256u) ? gx : 0;
        const void* src = &g_in[PLANE(p & 1, p >> 1, b) +
                                (((size_t)(ysc * 256 + gxc)) << 6) + c8 * 8];
        u32 dst = sb + slot + (u32)(p * 8448 + px * 128) +
                  (u32)((c8 * 16) ^ ((px & 7) << 4));
        cpa16(dst, src, ok);
    }
}

__global__ __launch_bounds__(256, 1)
void conv1_kernel() {
    extern __shared__ __align__(16) unsigned char sm[];
    u32 sb = smem_u32(sm);
    int tid = threadIdx.x, lane = tid & 31, wid = tid >> 5;
    int b = blockIdx.z, y0 = blockIdx.y * 32, x0 = blockIdx.x * 64;

    for (int i = tid; i < 73728 / 16; i += 256)
        ((uint4*)sm)[i] = ((const uint4*)g_Wc1)[i];

    int i8 = lane & 7, a_mh = (lane >> 3) & 1, a_kh = lane >> 4;
    int bq = lane >> 3;
    int wm = wid & 3, wn = wid >> 2;
    int apx = wm * 16 + a_mh * 8 + i8;
    int ocw2 = wn * 8 + i8;
    u32 bRow = (u32)(ocw2 * 256), kxor = (u32)((ocw2 & 7) << 4);
    int g = lane >> 2, t4 = lane & 3;

    c1_stage(sb, b, x0, y0 - 1, C1_SLOT0 + (u32)((-1) & 3) * C1_SLOTSZ, tid);
    c1_stage(sb, b, x0, y0 + 0, C1_SLOT0 + 0 * C1_SLOTSZ, tid);
    c1_stage(sb, b, x0, y0 + 1, C1_SLOT0 + 1 * C1_SLOTSZ, tid);
    CP_COMMIT();

    for (int y = 0; y < 32; y++) {
        CP_WAIT0();
        __syncthreads();
        if (y + 2 <= 32)
            c1_stage(sb, b, x0, y0 + y + 2, C1_SLOT0 + (u32)((y + 2) & 3) * C1_SLOTSZ, tid);
        CP_COMMIT();

        float acc[4] = {0.f, 0.f, 0.f, 0.f};
#pragma unroll
        for (int ky = 0; ky < 3; ky++) {
            u32 sl = sb + C1_SLOT0 + (u32)(((y + ky - 1) & 3)) * C1_SLOTSZ;
#pragma unroll
            for (int kx = 0; kx < 3; kx++) {
                int tap = ky * 3 + kx;
                int p = apx + kx;
                u32 aoff = (u32)(p * 128);
                u32 asw = (u32)((p & 7) << 4);
#pragma unroll
                for (int cg = 0; cg < 2; cg++) {
                    u32 pb2 = sl + (u32)(cg * 16896);
#pragma unroll
                    for (int pr = 0; pr < 2; pr++) {
                        u32 bA = sb + (u32)(tap * 4096) + bRow +
                                 ((u32)(cg * 128 + pr * 64 + bq * 16) ^ kxor);
                        u32 BH[4], BL[4];
                        ldm4(BH, bA);
                        ldm4(BL, bA + 36864);
#pragma unroll
                        for (int kcin = 0; kcin < 2; kcin++) {
                            int kc = pr * 2 + kcin;
                            u32 aH = pb2 + aoff + ((u32)(kc * 32 + a_kh * 16) ^ asw);
                            u32 Ah[4], Al[4];
                            ldm4(Ah, aH);
                            ldm4(Al, aH + 8448);
                            mma16816(acc, Ah, BH + 2 * kcin);
                            mma16816(acc, Al, BH + 2 * kcin);
                            mma16816(acc, Ah, BL + 2 * kcin);
                        }
                    }
                }
            }
        }
        // writeout: fp32 U + bf16 hi/lo
        int yy = y0 + y;
        int px = x0 + wm * 16 + g;
        int oc = wn * 8 + 2 * t4;
        size_t rowb = (size_t)yy * 256 + px;
        g_U[((size_t)(b * 16 + oc) << 16) + rowb] = acc[0];
        g_U[((size_t)(b * 16 + oc + 1) << 16) + rowb] = acc[1];
        g_U[((size_t)(b * 16 + oc) << 16) + rowb + 8] = acc[2];
        g_U[((size_t)(b * 16 + oc + 1) << 16) + rowb + 8] = acc[3];
        __nv_bfloat16 h0, l0, h1, l1;
        split(acc[0], h0, l0);
        split(acc[1], h1, l1);
        size_t idx = ((size_t)b * HWN + rowb) * 16 + oc;
        __nv_bfloat162 hh, ll;
        hh.x = h0; hh.y = h1; ll.x = l0; ll.y = l1;
        *(__nv_bfloat162*)&g_Uh[idx] = hh;
        *(__nv_bfloat162*)&g_Ul[idx] = ll;
        split(acc[2], h0, l0);
        split(acc[3], h1, l1);
        hh.x = h0; hh.y = h1; ll.x = l0; ll.y = l1;
        *(__nv_bfloat162*)&g_Uh[idx + 128] = hh;
        *(__nv_bfloat162*)&g_Ul[idx + 128] = ll;
    }
}

// ================= reduction (fp32, unchanged) =================
__global__ __launch_bounds__(256)
void reduce_kernel(const float* __restrict__ bridge) {
    __shared__ __align__(16) float sU[16][68];
    __shared__ __align__(16) float sB[64][68];
    int b = blockIdx.y, ch = blockIdx.x;
    int tid = threadIdx.x;
    int s = tid >> 4, q = tid & 15;
    int n0 = ch * 512;
    const float* Ub = g_U + (size_t)b * 16 * HWN;
    const float* Bb = bridge + (size_t)b * 64 * HWN;
    float accG[4] = {0.f, 0.f, 0.f, 0.f};
    float accM = 0.f, accR = 0.f;
    for (int sub = 0; sub < 8; sub++) {
        int n = n0 + sub * 64;
        {
            int sl = tid >> 4, p4 = (tid & 15) * 4;
            *reinterpret_cast<float4*>(&sU[sl][p4]) =
                *reinterpret_cast<const float4*>(&Ub[sl * HWN + n + p4]);
        }
#pragma unroll
        for (int r = 0; r < 4; r++) {
            int cl = (tid >> 4) + r * 16;
            int p4 = (tid & 15) * 4;
            *reinterpret_cast<float4*>(&sB[cl][p4]) =
                *reinterpret_cast<const float4*>(&Bb[cl * HWN + n + p4]);
        }
        __syncthreads();
#pragma unroll
        for (int p = 0; p < 64; p += 4) {
            float4 u = *reinterpret_cast<float4*>(&sU[s][p]);
            float4 t4 = *reinterpret_cast<float4*>(&sU[q][p]);
            accM += u.x * t4.x + u.y * t4.y + u.z * t4.z + u.w * t4.w;
#pragma unroll
            for (int j = 0; j < 4; j++) {
                float4 bv = *reinterpret_cast<float4*>(&sB[q + j * 16][p]);
                accG[j] += u.x * bv.x + u.y * bv.y + u.z * bv.z + u.w * bv.w;
            }
            if (q == 0) accR += fabsf(u.x) + fabsf(u.y) + fabsf(u.z) + fabsf(u.w);
        }
        __syncthreads();
    }
    float* o = g_part + (size_t)(b * NCHUNK + ch) * PART_STRIDE;
    o[s * 16 + q] = accM;
#pragma unroll
    for (int j = 0; j < 4; j++) o[256 + s * 64 + q + j * 16] = accG[j];
    if (q == 0) o[1280 + s] = accR;
}

// ================= solve (unchanged) =================
__global__ __launch_bounds__(256)
void solve_kernel() {
    __shared__ float sGram[256];
    __shared__ float sG[1024];
    __shared__ float srr[16];
    __shared__ double A[16][17];
    __shared__ double M[16][17];
    __shared__ double spiv;
    int b = blockIdx.x;
    int tid = threadIdx.x;
    const float* base = g_part + (size_t)b * NCHUNK * PART_STRIDE;
    {
        float a = 0.f;
        for (int ch = 0; ch < NCHUNK; ch++) a += base[ch * PART_STRIDE + tid];
        sGram[tid] = a;
    }
#pragma unroll
    for (int j = 0; j < 4; j++) {
        int e = tid + j * 256;
        float a = 0.f;
        for (int ch = 0; ch < NCHUNK; ch++) a += base[ch * PART_STRIDE + 256 + e];
        sG[e] = a;
    }
    if (tid < 16) {
        float a = 0.f;
        for (int ch = 0; ch < NCHUNK; ch++) a += base[ch * PART_STRIDE + 1280 + tid];
        srr[tid] = 1e-6f + a;
    }
    __syncthreads();
    {
        int i = tid >> 4, t = tid & 15;
        A[i][t] = (double)sGram[tid] / ((double)srr[i] * (double)srr[t]);
        M[i][t] = (i == t) ? 1.0 : 0.0;
    }
    __syncthreads();
    for (int k = 0; k < 16; k++) {
        if (tid == 0) spiv = 1.0 / A[k][k];
        __syncthreads();
        if (tid < 16) { A[k][tid] *= spiv; M[k][tid] *= spiv; }
        __syncthreads();
        int i = tid >> 4, t = tid & 15;
        double f = A[i][k];
        __syncthreads();
        if (i != k) { A[i][t] -= f * A[k][t]; M[i][t] -= f * M[k][t]; }
        __syncthreads();
    }
#pragma unroll
    for (int j = 0; j < 4; j++) {
        int e = tid + j * 256;
        int s = e >> 6, c = e & 63;
        double v = 0.0;
#pragma unroll
        for (int t = 0; t < 16; t++)
            v += M[s][t] * ((double)sG[t * 64 + c] / (double)srr[t]);
        g_PF2[b * 1024 + e] = (float)(v / (double)srr[s]);
    }
}

// ================= fold PF2 into conv2 proj-weights =================
__global__ __launch_bounds__(256)
void w2eff_kernel(const float* __restrict__ Wc) {
    __shared__ float sPF[1024];
    int b = blockIdx.x, tid = threadIdx.x;
    for (int i = tid; i < 1024; i += 256) sPF[i] = g_PF2[b * 1024 + i];
    __syncthreads();
    for (int e = tid; e < 9216; e += 256) {
        int tap = e / 1024, r = e & 1023, o = r >> 4, s = r & 15;
        float v = 0.f;
#pragma unroll
        for (int c = 0; c < 64; c++)
            v += Wc[o * 1152 + (64 + c) * 9 + tap] * sPF[s * 64 + c];
        __nv_bfloat16 h, l;
        split(v, h, l);
        g_W2[(size_t)b * 18432 + (size_t)(tap * 1024 + o * 16 + s)] = h;
        g_W2[(size_t)b * 18432 + (size_t)(9216 + tap * 1024 + o * 16 + s)] = l;
    }
}

// ================= conv2: strip 32px x 32y, 4-slot row rotation =================
#define C2_SLOT0 184320
#define C2_SLOTSZ 10880

__device__ __forceinline__ void c2_stage(u32 sb, int b, int x0, int ys, u32 slot, int tid) {
    bool yok = (unsigned)ys < 256u;
    int ysc = yok ? ys : 0;
    for (int i = tid; i < 680; i += 256) {
        if (i < 544) {
            int var = i >= 272;
            int j = i - var * 272;
            int px = j >> 3, c8 = j & 7;
            int gx = x0 - 1 + px;
            bool ok = yok && (unsigned)gx < 256u;
            int gxc = ((unsigned)gx < 256u) ? gx : 0;
            const void* src = &g_in[PLANE(var, 0, b) +
                                    (((size_t)(ysc * 256 + gxc)) << 6) + c8 * 8];
            u32 dst = sb + slot + (u32)(var * 4352 + px * 128) +
                      (u32)((c8 * 16) ^ ((px & 7) << 4));
            cpa16(dst, src, ok);
        } else {
            int j = i - 544;
            int var = j >= 68;
            int jj = j - var * 68;
            int px = jj >> 1, hf = jj & 1;
            int gx = x0 - 1 + px;
            bool ok = yok && (unsigned)gx < 256u;
            int gxc = ((unsigned)gx < 256u) ? gx : 0;
            const __nv_bfloat16* bp = var ? g_Ul : g_Uh;
            const void* src = &bp[((size_t)b * HWN + (size_t)(ysc * 256 + gxc)) * 16 + hf * 8];
            u32 dst = sb + slot + 8704 + (u32)(var * 1088 + px * 32 + hf * 16);
            cpa16(dst, src, ok);
        }
    }
}

__global__ __launch_bounds__(256, 1)
void conv2_kernel(const float* __restrict__ x, float* __restrict__ out) {
    extern __shared__ __align__(16) unsigned char sm[];
    u32 sb = smem_u32(sm);
    int tid = threadIdx.x, lane = tid & 31, wid = tid >> 5;
    int b = blockIdx.z, y0 = blockIdx.y * 32, x0 = blockIdx.x * 32;

    for (int i = tid; i < 147456 / 16; i += 256)
        ((uint4*)sm)[i] = ((const uint4*)g_Wc2)[i];
    for (int i = tid; i < 36864 / 16; i += 256)
        ((uint4*)(sm + 147456))[i] = ((const uint4*)(g_W2 + (size_t)b * 18432))[i];

    int i8 = lane & 7, a_mh = (lane >> 3) & 1, a_kh = lane >> 4;
    int b_kh = (lane >> 3) & 1, b_nh = lane >> 4;
    int wm = wid & 1, wn = wid >> 1;
    int apx = wm * 16 + a_mh * 8 + i8;
    int ocw = wn * 16 + b_nh * 8 + i8;
    u32 bRow = (u32)(ocw * 128), bSw = (u32)((ocw & 7) << 4);
    u32 bRowU = (u32)(ocw * 32);
    int g = lane >> 2, t4 = lane & 3;

    c2_stage(sb, b, x0, y0 - 1, C2_SLOT0 + (u32)((-1) & 3) * C2_SLOTSZ, tid);
    c2_stage(sb, b, x0, y0 + 0, C2_SLOT0 + 0 * C2_SLOTSZ, tid);
    c2_stage(sb, b, x0, y0 + 1, C2_SLOT0 + 1 * C2_SLOTSZ, tid);
    CP_COMMIT();

    for (int y = 0; y < 32; y++) {
        CP_WAIT0();
        __syncthreads();
        if (y + 2 <= 32)
            c2_stage(sb, b, x0, y0 + y + 2, C2_SLOT0 + (u32)((y + 2) & 3) * C2_SLOTSZ, tid);
        CP_COMMIT();

        float acc[2][4];
#pragma unroll
        for (int j = 0; j < 2; j++)
#pragma unroll
            for (int q = 0; q < 4; q++) acc[j][q] = 0.f;

#pragma unroll
        for (int ky = 0; ky < 3; ky++) {
            u32 sl = sb + C2_SLOT0 + (u32)(((y + ky - 1) & 3)) * C2_SLOTSZ;
#pragma unroll
            for (int kx = 0; kx < 3; kx++) {
                int tap = ky * 3 + kx;
                int p = apx + kx;
                u32 aoff = (u32)(p * 128);
                u32 asw = (u32)((p & 7) << 4);
#pragma unroll
                for (int kc = 0; kc < 4; kc++) {
                    u32 aH = sl + aoff + ((u32)(kc * 32 + a_kh * 16) ^ asw);
                    u32 Ah[4], Al[4], BH[4], BL[4];
                    ldm4(Ah, aH);
                    ldm4(Al, aH + 4352);
                    u32 bA = sb + (u32)(tap * 8192) + bRow +
                             ((u32)(kc * 32 + b_kh * 16) ^ bSw);
                    ldm4(BH, bA);
                    ldm4(BL, bA + 73728);
#pragma unroll
                    for (int j = 0; j < 2; j++) {
                        mma16816(acc[j], Ah, BH + 2 * j);
                        mma16816(acc[j], Al, BH + 2 * j);
                        mma16816(acc[j], Ah, BL + 2 * j);
                    }
                }
                // U part (k16 over 16 subspace channels)
                {
                    u32 aU = sl + 8704 + (u32)(p * 32 + a_kh * 16);
                    u32 AUh[4], AUl[4], BUh[4], BUl[4];
                    ldm4(AUh, aU);
                    ldm4(AUl, aU + 1088);
                    u32 bU = sb + 147456 + (u32)(tap * 2048) + bRowU + (u32)(b_kh * 16);
                    ldm4(BUh, bU);
                    ldm4(BUl, bU + 18432);
#pragma unroll
                    for (int j = 0; j < 2; j++) {
                        mma16816(acc[j], AUh, BUh + 2 * j);
                        mma16816(acc[j], AUl, BUh + 2 * j);
                        mma16816(acc[j], AUh, BUl + 2 * j);
                    }
                }
            }
        }
        // writeout + residual
        int yy = y0 + y;
        int px = x0 + wm * 16 + g;
        size_t rowb = (size_t)yy * 256 + px;
#pragma unroll
        for (int j = 0; j < 2; j++) {
            int oc = wn * 16 + j * 8 + 2 * t4;
            size_t o0 = ((size_t)(b * 64 + oc) << 16) + rowb;
            size_t o1 = o0 + HWN;
            out[o0] = acc[j][0] + x[o0];
            out[o1] = acc[j][1] + x[o1];
            out[o0 + 8] = acc[j][2] + x[o0 + 8];
            out[o1 + 8] = acc[j][3] + x[o1 + 8];
        }
    }
}

// ================= launch =================
extern "C" void kernel_launch(void* const* d_in, const int* in_sizes, int n_in,
                              void* d_out, int out_size) {
    const float* x      = (const float*)d_in[0];
    const float* bridge = (const float*)d_in[1];
    const float* Wsub   = (const float*)d_in[2];
    const float* Wcb    = (const float*)d_in[3];
    float* out = (float*)d_out;

    cudaFuncSetAttribute(conv1_kernel, cudaFuncAttributeMaxDynamicSharedMemorySize, 208896);
    cudaFuncSetAttribute(conv2_kernel, cudaFuncAttributeMaxDynamicSharedMemorySize, 227840);

    prep_w_kernel<<<288, 256>>>(Wsub, Wcb);
    convert_kernel<<<dim3(1024, 2, 8), 256>>>(x, bridge);
    conv1_kernel<<<dim3(4, 8, 8), 256, 208896>>>();
    reduce_kernel<<<dim3(NCHUNK, BB), 256>>>(bridge);
    solve_kernel<<<BB, 256>>>();
    w2eff_kernel<<<BB, 256>>>(Wcb);
    conv2_kernel<<<dim3(8, 8, 8), 256, 227840>>>(x, out);
}